// round 15
// baseline (speedup 1.0000x reference)
#include <cuda_runtime.h>
#include <cuda_fp16.h>
#include <cstdint>

#define IM_HW   16384          // 128*128 pixels
#define BC      64             // B*C channels
#define NB      10980          // 183*60 HT bins
#define NV      983040         // votes (= 960*256*4 exactly)
#define CAP     256            // per-bin capacity (mean 89.5, sigma 9.4 -> 17 sigma)
#define TBLK    512            // transpose blocks in fused prep kernel
#define FBLK    960            // fill blocks (4 votes/thread)
#define SCAP    192            // smem-staged pairs per bin (mean + 11 sigma)

__device__ __forceinline__ __half2 u2h2(unsigned u) {
    union { unsigned u; __half2 h; } c; c.u = u; return c.h;
}
__device__ __forceinline__ unsigned h22u(__half2 h) {
    union { unsigned u; __half2 h; } c; c.h = h; return c.u;
}

// -------- persistent scratch (__device__ globals; zero-initialized) --------
__device__ uint4 d_xh[IM_HW * 8];             // fp16 image [pix][64ch] = 128B/row (2 MB)
__device__ int   d_cursor[NB];                // per-bin count; re-zeroed by gather
__device__ uint2 d_pairs[NB * CAP];           // (pix*128, bits(w_fp32)) per slot (22.5 MB)
__device__ int   d_ovf_cnt;
__device__ uint4 d_ovf[4096];                 // overflow spill (pix<<7, wbits_f32, bin, 0)

__device__ __forceinline__ void vote_store(float fp, float fh, float fw) {
    int pix = (int)fp;
    int bin = (int)fh;
    int pos = atomicAdd(&d_cursor[bin], 1);
    if (pos < CAP) {
        d_pairs[bin * CAP + pos] = make_uint2((unsigned)(pix << 7), __float_as_uint(fw));
    } else {
        int o = atomicAdd(&d_ovf_cnt, 1);
        if (o < 4096)
            d_ovf[o] = make_uint4((unsigned)(pix << 7), __float_as_uint(fw),
                                  (unsigned)bin, 0u);
    }
}

// -------- 1. fused prep: transpose+fp16 (blocks 0..511) || fill (blocks 512+) --------
__global__ void __launch_bounds__(256) prep_kernel(const float* __restrict__ im,
                                                   const float* __restrict__ vm) {
    if (blockIdx.x < TBLK) {
        __shared__ float tile[32][68];        // pitch 272B -> float4-aligned rows
        int pixbase = blockIdx.x * 32;
        int t  = threadIdx.x;
        int tx = t & 31;
        int ty = t >> 5;
        #pragma unroll
        for (int b0 = 0; b0 < BC; b0 += 8)
            tile[tx][b0 + ty] = im[(b0 + ty) * IM_HW + pixbase + tx];   // coalesced
        __syncthreads();
        int p  = t >> 3;
        int c0 = (t & 7) * 8;
        float4 a = *(float4*)&tile[p][c0];
        float4 b = *(float4*)&tile[p][c0 + 4];
        uint4 hv;
        hv.x = h22u(__float22half2_rn(make_float2(a.x, a.y)));
        hv.y = h22u(__float22half2_rn(make_float2(a.z, a.w)));
        hv.z = h22u(__float22half2_rn(make_float2(b.x, b.y)));
        hv.w = h22u(__float22half2_rn(make_float2(b.z, b.w)));
        *(uint4*)((char*)d_xh + (pixbase + p) * 128 + c0 * 2) = hv;
    } else {
        // ---- fill: 4 votes per thread via 3 coalesced float4 loads ----
        int t = (blockIdx.x - TBLK) * 256 + threadIdx.x;   // < 245760
        const float4* vm4 = (const float4*)vm + (size_t)t * 3;
        float4 a = __ldg(vm4);
        float4 b = __ldg(vm4 + 1);
        float4 c = __ldg(vm4 + 2);
        vote_store(a.x, a.y, a.z);
        vote_store(a.w, b.x, b.y);
        vote_store(b.z, b.w, c.x);
        vote_store(c.y, c.z, c.w);
    }
}

// 8-channel fp16 FMA into fp32 accumulators
__device__ __forceinline__ void fma8(float* acc, uint4 xv, float wgt) {
    float2 f0 = __half22float2(u2h2(xv.x));
    float2 f1 = __half22float2(u2h2(xv.y));
    float2 f2 = __half22float2(u2h2(xv.z));
    float2 f3 = __half22float2(u2h2(xv.w));
    acc[0] = fmaf(wgt, f0.x, acc[0]);
    acc[1] = fmaf(wgt, f0.y, acc[1]);
    acc[2] = fmaf(wgt, f1.x, acc[2]);
    acc[3] = fmaf(wgt, f1.y, acc[3]);
    acc[4] = fmaf(wgt, f2.x, acc[4]);
    acc[5] = fmaf(wgt, f2.y, acc[5]);
    acc[6] = fmaf(wgt, f3.x, acc[6]);
    acc[7] = fmaf(wgt, f3.y, acc[7]);
}

// -------- 2. hot kernel: smem-pairs + MLP-8 segmented gather-reduce --------
// One warp per bin. The warp stages its bin's pairs into smem (coalesced,
// __syncwarp only — no cross-warp coupling), so the hot loop's pair source
// is a 29-cyc LDS, not a 234-cyc L2 load. Quarter q handles votes i%4==q;
// lane owns 8 channels (LDG.128). Batch-8 keeps 8 independent lines in flight.
__global__ void __launch_bounds__(256, 4) gather_kernel(float* __restrict__ out) {
    __shared__ uint2 spairs[8][SCAP];         // 12 KB
    __shared__ float sout[BC][8];             // [channel][bin-in-block]
    int warp = threadIdx.x >> 5;
    int lane = threadIdx.x & 31;
    int bin0 = blockIdx.x * 8;
    int bin  = bin0 + warp;

    float acc[8] = {0.f, 0.f, 0.f, 0.f, 0.f, 0.f, 0.f, 0.f};
    if (bin < NB) {
        int novf = d_ovf_cnt;
        int cnt  = d_cursor[bin];
        if (cnt > CAP) cnt = CAP;
        const uint2* pp = d_pairs + (size_t)bin * CAP;
        int lim = cnt < SCAP ? cnt : SCAP;
        for (int i = lane; i < lim; i += 32)              // coalesced stage
            spairs[warp][i] = __ldg(&pp[i]);
        __syncwarp();

        int q = lane >> 3;                    // 0..3
        const char* xb = (const char*)d_xh + (lane & 7) * 16;   // 8 fp16 channels
        int i = q;
        // batch-8: pairs from smem (LDS), 8 independent 128B x-lines in flight
        for (; i + 28 < lim; i += 32) {
            uint2 p0 = spairs[warp][i];
            uint2 p1 = spairs[warp][i + 4];
            uint2 p2 = spairs[warp][i + 8];
            uint2 p3 = spairs[warp][i + 12];
            uint2 p4 = spairs[warp][i + 16];
            uint2 p5 = spairs[warp][i + 20];
            uint2 p6 = spairs[warp][i + 24];
            uint2 p7 = spairs[warp][i + 28];
            uint4 x0 = *(const uint4*)(xb + p0.x);
            uint4 x1 = *(const uint4*)(xb + p1.x);
            uint4 x2 = *(const uint4*)(xb + p2.x);
            uint4 x3 = *(const uint4*)(xb + p3.x);
            uint4 x4 = *(const uint4*)(xb + p4.x);
            uint4 x5 = *(const uint4*)(xb + p5.x);
            uint4 x6 = *(const uint4*)(xb + p6.x);
            uint4 x7 = *(const uint4*)(xb + p7.x);
            fma8(acc, x0, __uint_as_float(p0.y));
            fma8(acc, x1, __uint_as_float(p1.y));
            fma8(acc, x2, __uint_as_float(p2.y));
            fma8(acc, x3, __uint_as_float(p3.y));
            fma8(acc, x4, __uint_as_float(p4.y));
            fma8(acc, x5, __uint_as_float(p5.y));
            fma8(acc, x6, __uint_as_float(p6.y));
            fma8(acc, x7, __uint_as_float(p7.y));
        }
        for (; i < lim; i += 4) {             // staged remainder
            uint2 pw = spairs[warp][i];
            uint4 xv = *(const uint4*)(xb + pw.x);
            fma8(acc, xv, __uint_as_float(pw.y));
        }
        for (; i < cnt; i += 4) {             // beyond SCAP (statistically never)
            uint2 pw = __ldg(&pp[i]);
            uint4 xv = *(const uint4*)(xb + pw.x);
            fma8(acc, xv, __uint_as_float(pw.y));
        }
        // inline overflow spill (statistically unreachable; correct if hit)
        if (novf > 4096) novf = 4096;
        for (int j = 0; j < novf; j++) {
            uint4 ov = d_ovf[j];
            if ((int)ov.z == bin && q == 0) {
                uint4 xv = *(const uint4*)(xb + ov.x);
                fma8(acc, xv, __uint_as_float(ov.y));
            }
        }
        if (lane == 0) d_cursor[bin] = 0;     // reset for next replay (sole reader)
    }
    if (blockIdx.x == 0 && threadIdx.x == 0) d_ovf_cnt = 0;

    // combine the four quarter-warps
    #pragma unroll
    for (int k = 0; k < 8; k++) {
        acc[k] += __shfl_xor_sync(0xffffffffu, acc[k], 8);
        acc[k] += __shfl_xor_sync(0xffffffffu, acc[k], 16);
    }
    if (lane < 8) {
        #pragma unroll
        for (int k = 0; k < 8; k++) sout[lane * 8 + k][warp] = acc[k];
    }
    __syncthreads();
    // coalesced write: thread t -> out[(t>>3)*NB + bin0 + (t&7)]
    int c = threadIdx.x >> 3;
    int b = threadIdx.x & 7;
    if (bin0 + b < NB) {
        out[c * NB + bin0 + b]        = sout[c][b];
        out[(c + 32) * NB + bin0 + b] = sout[c + 32][b];
    }
}

// -------- launch --------
extern "C" void kernel_launch(void* const* d_in, const int* in_sizes, int n_in,
                              void* d_out, int out_size) {
    const float* im = (const float*)d_in[0];
    const float* vm = (const float*)d_in[1];
    if (in_sizes[0] == NV * 3) { im = (const float*)d_in[1]; vm = (const float*)d_in[0]; }
    float* out = (float*)d_out;

    prep_kernel<<<TBLK + FBLK, 256>>>(im, vm);
    gather_kernel<<<(NB + 7) / 8, 256>>>(out);
}

// round 16
// speedup vs baseline: 1.2314x; 1.2314x over previous
#include <cuda_runtime.h>
#include <cuda_fp16.h>
#include <cstdint>

#define IM_HW   16384          // 128*128 pixels
#define BC      64             // B*C channels
#define NB      10980          // 183*60 HT bins
#define NV      983040         // votes (= 3840*256 exactly)
#define CAP     256            // per-bin capacity (mean 89.5, sigma 9.4 -> 17 sigma)
#define TBLK    512            // transpose blocks in fused prep kernel
#define SCAP    192            // smem-staged pairs per bin (mean + 11 sigma)
#define CSTRIDE 32             // cursor padding: 1 counter per 128B L2 line

__device__ __forceinline__ __half2 u2h2(unsigned u) {
    union { unsigned u; __half2 h; } c; c.u = u; return c.h;
}
__device__ __forceinline__ unsigned h22u(__half2 h) {
    union { unsigned u; __half2 h; } c; c.h = h; return c.u;
}

// -------- persistent scratch (__device__ globals; zero-initialized) --------
__device__ uint4 d_xh[IM_HW * 8];             // fp16 image [pix][64ch] = 128B/row (2 MB)
__device__ int   d_cursor[NB * CSTRIDE];      // padded: bin -> bin*32 (1.4 MB)
__device__ uint2 d_pairs[NB * CAP];           // (pix*128, bits(w_fp32)) per slot (22.5 MB)
__device__ int   d_ovf_cnt;
__device__ uint4 d_ovf[4096];                 // overflow spill (pix<<7, wbits_f32, bin, 0)

// -------- 1. fused prep: transpose+fp16 (blocks 0..511) || fill (blocks 512+) --------
__global__ void __launch_bounds__(256) prep_kernel(const float* __restrict__ im,
                                                   const float* __restrict__ vm) {
    if (blockIdx.x < TBLK) {
        __shared__ float tile[32][68];        // pitch 272B -> float4-aligned rows
        int pixbase = blockIdx.x * 32;
        int t  = threadIdx.x;
        int tx = t & 31;
        int ty = t >> 5;
        #pragma unroll
        for (int b0 = 0; b0 < BC; b0 += 8)
            tile[tx][b0 + ty] = im[(b0 + ty) * IM_HW + pixbase + tx];   // coalesced
        __syncthreads();
        int p  = t >> 3;
        int c0 = (t & 7) * 8;
        float4 a = *(float4*)&tile[p][c0];
        float4 b = *(float4*)&tile[p][c0 + 4];
        uint4 hv;
        hv.x = h22u(__float22half2_rn(make_float2(a.x, a.y)));
        hv.y = h22u(__float22half2_rn(make_float2(a.z, a.w)));
        hv.z = h22u(__float22half2_rn(make_float2(b.x, b.y)));
        hv.w = h22u(__float22half2_rn(make_float2(b.z, b.w)));
        *(uint4*)((char*)d_xh + (pixbase + p) * 128 + c0 * 2) = hv;
    } else {
        int v = (blockIdx.x - TBLK) * 256 + threadIdx.x;   // < NV by construction
        float fp = __ldg(&vm[v * 3 + 0]);
        float fh = __ldg(&vm[v * 3 + 1]);
        float fw = __ldg(&vm[v * 3 + 2]);
        int pix = (int)fp;
        int bin = (int)fh;
        // padded counter: one per 128B line -> no L2 line-level atomic serialization
        int pos = atomicAdd(&d_cursor[bin * CSTRIDE], 1);
        if (pos < CAP) {
            d_pairs[bin * CAP + pos] = make_uint2((unsigned)(pix << 7), __float_as_uint(fw));
        } else {
            int o = atomicAdd(&d_ovf_cnt, 1);
            if (o < 4096)
                d_ovf[o] = make_uint4((unsigned)(pix << 7), __float_as_uint(fw),
                                      (unsigned)bin, 0u);
        }
    }
}

// 8-channel fp16 FMA into fp32 accumulators
__device__ __forceinline__ void fma8(float* acc, uint4 xv, float wgt) {
    float2 f0 = __half22float2(u2h2(xv.x));
    float2 f1 = __half22float2(u2h2(xv.y));
    float2 f2 = __half22float2(u2h2(xv.z));
    float2 f3 = __half22float2(u2h2(xv.w));
    acc[0] = fmaf(wgt, f0.x, acc[0]);
    acc[1] = fmaf(wgt, f0.y, acc[1]);
    acc[2] = fmaf(wgt, f1.x, acc[2]);
    acc[3] = fmaf(wgt, f1.y, acc[3]);
    acc[4] = fmaf(wgt, f2.x, acc[4]);
    acc[5] = fmaf(wgt, f2.y, acc[5]);
    acc[6] = fmaf(wgt, f3.x, acc[6]);
    acc[7] = fmaf(wgt, f3.y, acc[7]);
}

// -------- 2. hot kernel: smem-pairs + MLP-8 segmented gather-reduce --------
// One warp per bin. The warp stages its bin's pairs into smem (coalesced,
// __syncwarp only), so hot-loop pair reads are 29-cyc LDS, not 234-cyc L2.
// Quarter q handles votes i%4==q; lane owns 8 channels (LDG.128). Batch-8
// keeps 8 independent 128B lines in flight per warp.
__global__ void __launch_bounds__(256, 4) gather_kernel(float* __restrict__ out) {
    __shared__ uint2 spairs[8][SCAP];         // 12 KB
    __shared__ float sout[BC][8];             // [channel][bin-in-block]
    int warp = threadIdx.x >> 5;
    int lane = threadIdx.x & 31;
    int bin0 = blockIdx.x * 8;
    int bin  = bin0 + warp;

    float acc[8] = {0.f, 0.f, 0.f, 0.f, 0.f, 0.f, 0.f, 0.f};
    if (bin < NB) {
        int novf = d_ovf_cnt;
        int cnt  = d_cursor[bin * CSTRIDE];
        if (cnt > CAP) cnt = CAP;
        const uint2* pp = d_pairs + (size_t)bin * CAP;
        int lim = cnt < SCAP ? cnt : SCAP;
        for (int i = lane; i < lim; i += 32)              // coalesced stage
            spairs[warp][i] = __ldg(&pp[i]);
        __syncwarp();

        int q = lane >> 3;                    // 0..3
        const char* xb = (const char*)d_xh + (lane & 7) * 16;   // 8 fp16 channels
        int i = q;
        // batch-8: pairs from smem (LDS), 8 independent 128B x-lines in flight
        for (; i + 28 < lim; i += 32) {
            uint2 p0 = spairs[warp][i];
            uint2 p1 = spairs[warp][i + 4];
            uint2 p2 = spairs[warp][i + 8];
            uint2 p3 = spairs[warp][i + 12];
            uint2 p4 = spairs[warp][i + 16];
            uint2 p5 = spairs[warp][i + 20];
            uint2 p6 = spairs[warp][i + 24];
            uint2 p7 = spairs[warp][i + 28];
            uint4 x0 = *(const uint4*)(xb + p0.x);
            uint4 x1 = *(const uint4*)(xb + p1.x);
            uint4 x2 = *(const uint4*)(xb + p2.x);
            uint4 x3 = *(const uint4*)(xb + p3.x);
            uint4 x4 = *(const uint4*)(xb + p4.x);
            uint4 x5 = *(const uint4*)(xb + p5.x);
            uint4 x6 = *(const uint4*)(xb + p6.x);
            uint4 x7 = *(const uint4*)(xb + p7.x);
            fma8(acc, x0, __uint_as_float(p0.y));
            fma8(acc, x1, __uint_as_float(p1.y));
            fma8(acc, x2, __uint_as_float(p2.y));
            fma8(acc, x3, __uint_as_float(p3.y));
            fma8(acc, x4, __uint_as_float(p4.y));
            fma8(acc, x5, __uint_as_float(p5.y));
            fma8(acc, x6, __uint_as_float(p6.y));
            fma8(acc, x7, __uint_as_float(p7.y));
        }
        for (; i < lim; i += 4) {             // staged remainder
            uint2 pw = spairs[warp][i];
            uint4 xv = *(const uint4*)(xb + pw.x);
            fma8(acc, xv, __uint_as_float(pw.y));
        }
        for (; i < cnt; i += 4) {             // beyond SCAP (statistically never)
            uint2 pw = __ldg(&pp[i]);
            uint4 xv = *(const uint4*)(xb + pw.x);
            fma8(acc, xv, __uint_as_float(pw.y));
        }
        // inline overflow spill (statistically unreachable; correct if hit)
        if (novf > 4096) novf = 4096;
        for (int j = 0; j < novf; j++) {
            uint4 ov = d_ovf[j];
            if ((int)ov.z == bin && q == 0) {
                uint4 xv = *(const uint4*)(xb + ov.x);
                fma8(acc, xv, __uint_as_float(ov.y));
            }
        }
        if (lane == 0) d_cursor[bin * CSTRIDE] = 0;   // reset for next replay
    }
    if (blockIdx.x == 0 && threadIdx.x == 0) d_ovf_cnt = 0;

    // combine the four quarter-warps
    #pragma unroll
    for (int k = 0; k < 8; k++) {
        acc[k] += __shfl_xor_sync(0xffffffffu, acc[k], 8);
        acc[k] += __shfl_xor_sync(0xffffffffu, acc[k], 16);
    }
    if (lane < 8) {
        #pragma unroll
        for (int k = 0; k < 8; k++) sout[lane * 8 + k][warp] = acc[k];
    }
    __syncthreads();
    // coalesced write: thread t -> out[(t>>3)*NB + bin0 + (t&7)]
    int c = threadIdx.x >> 3;
    int b = threadIdx.x & 7;
    if (bin0 + b < NB) {
        out[c * NB + bin0 + b]        = sout[c][b];
        out[(c + 32) * NB + bin0 + b] = sout[c + 32][b];
    }
}

// -------- launch --------
extern "C" void kernel_launch(void* const* d_in, const int* in_sizes, int n_in,
                              void* d_out, int out_size) {
    const float* im = (const float*)d_in[0];
    const float* vm = (const float*)d_in[1];
    if (in_sizes[0] == NV * 3) { im = (const float*)d_in[1]; vm = (const float*)d_in[0]; }
    float* out = (float*)d_out;

    prep_kernel<<<TBLK + NV / 256, 256>>>(im, vm);
    gather_kernel<<<(NB + 7) / 8, 256>>>(out);
}